// round 9
// baseline (speedup 1.0000x reference)
#include <cuda_runtime.h>

typedef unsigned long long ull;
typedef unsigned int uint;

#define NTHREADS 256
#define RAYS 8
#define NBLOCKS 4096
#define B_TOTAL 32768
#define S_A 68     // stride (floats) for activation-layout tiles: A-frag loads conflict-free
#define S_W 72     // stride (floats) for weight tiles: B-frag loads conflict-free

// smem layout (floats)
#define OFF_ACT 0                  // 64*68 = 4352 each
#define OFF_Q   4352
#define OFF_K   8704
#define OFF_V   13056
#define OFF_CTX 17408
#define OFF_AO  21760
#define OFF_W0  26112              // 64*72 = 4608 each (fp32 weights)
#define OFF_W1  30720
#define OFF_W2  35328
#define OFF_W3  39936
#define OFF_P   44544              // probs 8x64
#define SMEM_FLOATS (44544 + 512)  // 45056 floats = 180224 B
#define SMEM_BYTES (SMEM_FLOATS * 4)

struct Params {
  const float *query, *latent, *W1, *b1;
  const float *Wq, *bq, *Wk, *bk, *Wv, *bv, *Wo, *bo;
  const float *fW1, *fb1, *fW2, *fb2, *g1, *be1, *g2, *be2;
  const float *cWq, *cbq, *cWk, *cbk, *cWv, *cbv, *cWo, *cbo;
  const float *Wc, *bc, *Ws, *bs;
  float *o_color, *o_sigma, *o_out, *o_attn;
};

// ---------------- small helpers ----------------
__device__ __forceinline__ float tf32c(float x) {
  uint u;
  asm("cvt.rna.tf32.f32 %0, %1;" : "=r"(u) : "f"(x));
  return __uint_as_float(u);
}
// split fp32 into tf32 hi + tf32 lo (3xTF32 decomposition)
__device__ __forceinline__ void split2(float x, uint& h, uint& l) {
  float hf = tf32c(x);
  h = __float_as_uint(hf);
  l = __float_as_uint(tf32c(x - hf));
}
__device__ __forceinline__ ull ffma2(ull a, ull b, ull c) {
  ull d;
  asm("fma.rn.f32x2 %0, %1, %2, %3;" : "=l"(d) : "l"(a), "l"(b), "l"(c));
  return d;
}
__device__ __forceinline__ ull pack2(float lo, float hi) {
  ull d;
  asm("mov.b64 %0, {%1, %2};" : "=l"(d) : "f"(lo), "f"(hi));
  return d;
}
__device__ __forceinline__ float2 unpack2(ull v) {
  float lo, hi;
  asm("mov.b64 {%0, %1}, %2;" : "=f"(lo), "=f"(hi) : "l"(v));
  return make_float2(lo, hi);
}

// m16n8k8 tf32 mma, D=C in place
__device__ __forceinline__ void mma8(float c[4], uint a0, uint a1, uint a2, uint a3,
                                     uint b0, uint b1) {
  asm("mma.sync.aligned.m16n8k8.row.col.f32.tf32.tf32.f32 "
      "{%0,%1,%2,%3},{%4,%5,%6,%7},{%8,%9},{%0,%1,%2,%3};"
      : "+f"(c[0]), "+f"(c[1]), "+f"(c[2]), "+f"(c[3])
      : "r"(a0), "r"(a1), "r"(a2), "r"(a3), "r"(b0), "r"(b1));
}

// A fragment (hi/lo) for one 16x8 k-slab
struct AF { uint h[4], l[4]; };
__device__ __forceinline__ AF load_a(const float* __restrict__ A, int lane,
                                     int mt, int kk) {
  const int grp = lane >> 2, kq = lane & 3;
  const float* ar = A + (mt * 16 + grp) * S_A + kk * 8 + kq;
  AF f;
  split2(ar[0], f.h[0], f.l[0]);
  split2(ar[8 * S_A], f.h[1], f.l[1]);
  split2(ar[4], f.h[2], f.l[2]);
  split2(ar[8 * S_A + 4], f.h[3], f.l[3]);
  return f;
}

// 3xTF32 k8 step: c += a*w with fp32-grade accuracy (3 mmas)
__device__ __forceinline__ void mma3(float c[4], const AF& a, float w0, float w1) {
  uint b0h, b0l, b1h, b1l;
  split2(w0, b0h, b0l);
  split2(w1, b1h, b1l);
  mma8(c, a.h[0], a.h[1], a.h[2], a.h[3], b0h, b1h);
  mma8(c, a.l[0], a.l[1], a.l[2], a.l[3], b0h, b1h);
  mma8(c, a.h[0], a.h[1], a.h[2], a.h[3], b0l, b1l);
}

// C[64x64] += A[64x64] @ W[64x64]; A f32 smem [64][S_A]; W f32 smem [64][S_W].
__device__ __forceinline__ void gemm_acc(const float* __restrict__ A,
                                         const float* __restrict__ W,
                                         int lane, int mt, int nh, float c[4][4]) {
  const int grp = lane >> 2, kq = lane & 3;
  #pragma unroll
  for (int kk = 0; kk < 8; kk++) {
    AF a = load_a(A, lane, mt, kk);
    const float* wb = W + (kk * 8 + kq) * S_W + nh * 32 + grp;
    #pragma unroll
    for (int t = 0; t < 4; t++)
      mma3(c[t], a, wb[t * 8], wb[4 * S_W + t * 8]);
  }
}

// Fused: one A pass, three weight matrices (QKV)
__device__ __forceinline__ void gemm3_acc(const float* __restrict__ A,
                                          const float* __restrict__ W0,
                                          const float* __restrict__ W1,
                                          const float* __restrict__ W2,
                                          int lane, int mt, int nh,
                                          float c0[4][4], float c1[4][4],
                                          float c2[4][4]) {
  const int grp = lane >> 2, kq = lane & 3;
  #pragma unroll
  for (int kk = 0; kk < 8; kk++) {
    AF a = load_a(A, lane, mt, kk);
    const int off = (kk * 8 + kq) * S_W + nh * 32 + grp;
    const float* w0 = W0 + off;
    const float* w1 = W1 + off;
    const float* w2 = W2 + off;
    #pragma unroll
    for (int t = 0; t < 4; t++) {
      mma3(c0[t], a, w0[t * 8], w0[4 * S_W + t * 8]);
      mma3(c1[t], a, w1[t * 8], w1[4 * S_W + t * 8]);
      mma3(c2[t], a, w2[t * 8], w2[4 * S_W + t * 8]);
    }
  }
}

// Fused: one A pass, two weight matrices (cross K/V)
__device__ __forceinline__ void gemm2_acc(const float* __restrict__ A,
                                          const float* __restrict__ W0,
                                          const float* __restrict__ W1,
                                          int lane, int mt, int nh,
                                          float c0[4][4], float c1[4][4]) {
  const int grp = lane >> 2, kq = lane & 3;
  #pragma unroll
  for (int kk = 0; kk < 8; kk++) {
    AF a = load_a(A, lane, mt, kk);
    const int off = (kk * 8 + kq) * S_W + nh * 32 + grp;
    const float* w0 = W0 + off;
    const float* w1 = W1 + off;
    #pragma unroll
    for (int t = 0; t < 4; t++) {
      mma3(c0[t], a, w0[t * 8], w0[4 * S_W + t * 8]);
      mma3(c1[t], a, w1[t * 8], w1[4 * S_W + t * 8]);
    }
  }
}

// store C frags to smem [64][S_A] with bias, optional relu/residual
__device__ __forceinline__ void store_c(float* D, int lane, int mt, int nh,
                                        const float c[4][4], const float* bias,
                                        int do_relu, const float* resid) {
  const int grp = lane >> 2, kq = lane & 3;
  const int r = mt * 16 + grp;
  #pragma unroll
  for (int t = 0; t < 4; t++) {
    int col = nh * 32 + t * 8 + 2 * kq;
    float b0 = __ldg(bias + col), b1 = __ldg(bias + col + 1);
    float v0 = c[t][0] + b0, v1 = c[t][1] + b1;
    float v2 = c[t][2] + b0, v3 = c[t][3] + b1;
    if (resid) {
      v0 += resid[r * S_A + col];
      v1 += resid[r * S_A + col + 1];
      v2 += resid[(r + 8) * S_A + col];
      v3 += resid[(r + 8) * S_A + col + 1];
    }
    if (do_relu) {
      v0 = fmaxf(v0, 0.f); v1 = fmaxf(v1, 0.f);
      v2 = fmaxf(v2, 0.f); v3 = fmaxf(v3, 0.f);
    }
    *(float2*)(D + r * S_A + col) = make_float2(v0, v1);
    *(float2*)(D + (r + 8) * S_A + col) = make_float2(v2, v3);
  }
}

// stage 64x64 fp32 weight block into [64][S_W] smem
__device__ __forceinline__ void stage_w(const float* __restrict__ src, int stride,
                                        float* __restrict__ dst, int tid) {
  #pragma unroll
  for (int it = 0; it < 4; it++) {
    int i = tid + it * NTHREADS;
    int d = i >> 4, j = (i & 15) * 4;
    *(float4*)(dst + d * S_W + j) = *(const float4*)(src + d * stride + j);
  }
}

// LayerNorm of 8 rows of (s1 [+ s2]) -> dst rows; lane owns cols lane, lane+32
__device__ __forceinline__ void ln_rows(const float* s1, const float* s2,
                                        const float* g, const float* be,
                                        int lane, float* dst) {
  float gg0 = __ldg(g + lane), gg1 = __ldg(g + lane + 32);
  float bb0 = __ldg(be + lane), bb1 = __ldg(be + lane + 32);
  #pragma unroll
  for (int s = 0; s < 8; s++) {
    float x0 = s1[s * S_A + lane];
    float x1 = s1[s * S_A + lane + 32];
    if (s2) { x0 += s2[s * S_A + lane]; x1 += s2[s * S_A + lane + 32]; }
    float sum = x0 + x1;
    #pragma unroll
    for (int o = 16; o > 0; o >>= 1) sum += __shfl_xor_sync(0xffffffffu, sum, o);
    float mean = sum * 0.015625f;
    float d0 = x0 - mean, d1 = x1 - mean;
    float vs = d0 * d0 + d1 * d1;
    #pragma unroll
    for (int o = 16; o > 0; o >>= 1) vs += __shfl_xor_sync(0xffffffffu, vs, o);
    float rstd = rsqrtf(vs * 0.015625f + 1e-5f);
    dst[s * S_A + lane] = d0 * rstd * gg0 + bb0;
    dst[s * S_A + lane + 32] = d1 * rstd * gg1 + bb1;
  }
}

#define STAGE_LAT(DST, KC)                                                     \
  do {                                                                         \
    _Pragma("unroll")                                                          \
    for (int it_ = 0; it_ < 4; it_++) {                                        \
      int i_ = tid + it_ * NTHREADS;                                           \
      int row_ = i_ >> 4, j_ = (i_ & 15) * 4;                                  \
      *(float4*)((DST) + row_ * S_A + j_) =                                    \
          *(const float4*)(p.latent + (size_t)(bbase + (row_ >> 3)) * 4096 +   \
                           (row_ & 7) * 512 + (KC) * 64 + j_);                 \
    }                                                                          \
  } while (0)

__global__ void __launch_bounds__(NTHREADS, 1) rt_kernel(Params p) {
  extern __shared__ float sm[];
  const int tid = threadIdx.x;
  const int warp = tid >> 5, lane = tid & 31;
  const int mt = warp & 3, nh = warp >> 2;   // mma roles
  const int ray = warp;                      // scalar roles
  const int bbase = blockIdx.x * RAYS;
  const int b = bbase + ray;

  float* s_act = sm + OFF_ACT;
  float* s_q = sm + OFF_Q;
  float* s_k = sm + OFF_K;
  float* s_v = sm + OFF_V;
  float* s_ctx = sm + OFF_CTX;
  float* s_ao = sm + OFF_AO;
  float* s_w0 = sm + OFF_W0;
  float* s_w1 = sm + OFF_W1;
  float* s_w2 = sm + OFF_W2;
  float* s_w3 = sm + OFF_W3;
  float* my_p = sm + OFF_P + ray * 64;

  // ---------------- stage 0: act = relu(latent @ W1 + b1), K=512 ----------------
  {
    float* lat0 = s_q;
    float* lat1 = s_k;
    stage_w(p.W1, 64, s_w0, tid);
    STAGE_LAT(lat0, 0);
    __syncthreads();
    float c[4][4] = {};
    for (int kc = 0; kc < 8; kc++) {
      const float* lb = (kc & 1) ? lat1 : lat0;
      const float* wb = (kc & 1) ? s_w1 : s_w0;
      if (kc < 7) {
        stage_w(p.W1 + (kc + 1) * 4096, 64, (kc & 1) ? s_w0 : s_w1, tid);
        STAGE_LAT((kc & 1) ? lat0 : lat1, kc + 1);
      }
      gemm_acc(lb, wb, lane, mt, nh, c);
      __syncthreads();
    }
    store_c(s_act, lane, mt, nh, c, p.b1, 1, nullptr);
  }
  __syncthreads();

  // ---------------- 4 transformer layers ----------------
  for (int l = 0; l < 4; l++) {
    stage_w(p.Wq + l * 16384, 256, s_w0, tid);
    stage_w(p.Wk + l * 16384, 256, s_w1, tid);
    stage_w(p.Wv + l * 16384, 256, s_w2, tid);
    __syncthreads();

    float co[4][4] = {};   // out-proj accumulator across heads
    for (int h = 0; h < 4; h++) {
      // fused QKV (one A pass, tensor)
      {
        float cq[4][4] = {}, ck[4][4] = {}, cv[4][4] = {};
        gemm3_acc(s_act, s_w0, s_w1, s_w2, lane, mt, nh, cq, ck, cv);
        store_c(s_q, lane, mt, nh, cq, p.bq + l * 256 + h * 64, 0, nullptr);
        store_c(s_k, lane, mt, nh, ck, p.bk + l * 256 + h * 64, 0, nullptr);
        store_c(s_v, lane, mt, nh, cv, p.bv + l * 256 + h * 64, 0, nullptr);
      }
      __syncthreads();   // (A) QKV visible

      // stage next weights; LDG latency overlapped by attention below
      stage_w(p.Wo + l * 16384 + h * 4096, 64, s_w3, tid);
      if (h < 3) {
        stage_w(p.Wq + l * 16384 + (h + 1) * 64, 256, s_w0, tid);
        stage_w(p.Wk + l * 16384 + (h + 1) * 64, 256, s_w1, tid);
        stage_w(p.Wv + l * 16384 + (h + 1) * 64, 256, s_w2, tid);
      } else {
        stage_w(p.fW1 + l * 4096, 64, s_w0, tid);
        stage_w(p.fW2 + l * 4096, 64, s_w1, tid);
      }

      // ---- attention (scalar fp32, warp = ray) ----
      {
        const float* qb = s_q + ray * 8 * S_A;
        const float* kb = s_k + ray * 8 * S_A;
        const float* vb = s_v + ray * 8 * S_A;
        float pr[2];
        #pragma unroll
        for (int u = 0; u < 2; u++) {
          int idx = lane + u * 32;
          int qi = idx >> 3, ki = idx & 7;
          const float* qr = qb + qi * S_A;
          const float* kr = kb + ki * S_A;
          ull acc = pack2(0.f, 0.f);
          #pragma unroll
          for (int j = 0; j < 64; j += 4) {
            ulonglong2 qq = *(const ulonglong2*)(qr + j);
            ulonglong2 kk2 = *(const ulonglong2*)(kr + j);
            acc = ffma2(qq.x, kk2.x, acc);
            acc = ffma2(qq.y, kk2.y, acc);
          }
          float2 t = unpack2(acc);
          float sc = (t.x + t.y) * 0.125f;
          float m = sc;
          m = fmaxf(m, __shfl_xor_sync(0xffffffffu, m, 1));
          m = fmaxf(m, __shfl_xor_sync(0xffffffffu, m, 2));
          m = fmaxf(m, __shfl_xor_sync(0xffffffffu, m, 4));
          float e = __expf(sc - m);
          float se = e;
          se += __shfl_xor_sync(0xffffffffu, se, 1);
          se += __shfl_xor_sync(0xffffffffu, se, 2);
          se += __shfl_xor_sync(0xffffffffu, se, 4);
          pr[u] = __fdividef(e, se);
        }
        my_p[lane] = pr[0];
        my_p[lane + 32] = pr[1];
        size_t ab = (size_t)b * 1024 + (size_t)l * 256 + h * 64;
        p.o_attn[ab + lane] = pr[0];
        p.o_attn[ab + lane + 32] = pr[1];
        __syncwarp();
        // ctx = P @ V
        float cx[16];
        #pragma unroll
        for (int i = 0; i < 16; i++) cx[i] = 0.f;
        #pragma unroll
        for (int ki = 0; ki < 8; ki++) {
          float vx = vb[ki * S_A + lane];
          float vy = vb[ki * S_A + lane + 32];
          #pragma unroll
          for (int qi = 0; qi < 8; qi++) {
            float pk = my_p[qi * 8 + ki];
            cx[2 * qi] = fmaf(pk, vx, cx[2 * qi]);
            cx[2 * qi + 1] = fmaf(pk, vy, cx[2 * qi + 1]);
          }
        }
        float* cr = s_ctx + ray * 8 * S_A;
        #pragma unroll
        for (int qi = 0; qi < 8; qi++) {
          cr[qi * S_A + lane] = cx[2 * qi];
          cr[qi * S_A + lane + 32] = cx[2 * qi + 1];
        }
      }
      __syncthreads();   // (B) ctx + staged weights visible

      // out-proj: co += ctx @ Wo_h (tensor)
      gemm_acc(s_ctx, s_w3, lane, mt, nh, co);
      // no sync needed (see R8 reasoning): next writes hit q/k/v; ctx/w3
      // readers all precede sync-A of head h+1
    }  // heads

    store_c(s_ao, lane, mt, nh, co, p.bo + l * 64, 0, nullptr);
    __syncthreads();
    // LN1: act = LN(a_out + act)
    ln_rows(s_ao + ray * 8 * S_A, s_act + ray * 8 * S_A,
            p.g1 + l * 64, p.be1 + l * 64, lane, s_act + ray * 8 * S_A);
    __syncthreads();
    // FF1 (w0 = fW1 staged during h==3)
    {
      float c[4][4] = {};
      gemm_acc(s_act, s_w0, lane, mt, nh, c);
      store_c(s_q, lane, mt, nh, c, p.fb1 + l * 64, 1, nullptr);
    }
    __syncthreads();
    // FF2 + residual
    {
      float c[4][4] = {};
      gemm_acc(s_q, s_w1, lane, mt, nh, c);
      store_c(s_ao, lane, mt, nh, c, p.fb2 + l * 64, 0, s_act);
    }
    __syncthreads();
    // LN2: act = LN(a_out)
    ln_rows(s_ao + ray * 8 * S_A, nullptr,
            p.g2 + l * 64, p.be2 + l * 64, lane, s_act + ray * 8 * S_A);
    __syncthreads();
  }  // layers

  // ---------------- sigma & out ----------------
  {
    const float* ar = s_act + ray * 8 * S_A;
    float m0 = ar[lane], m1 = ar[lane + 32];
    #pragma unroll
    for (int s = 1; s < 8; s++) {
      m0 = fmaxf(m0, ar[s * S_A + lane]);
      m1 = fmaxf(m1, ar[s * S_A + lane + 32]);
    }
    float part = m0 * __ldg(p.Ws + lane) + m1 * __ldg(p.Ws + lane + 32);
    #pragma unroll
    for (int o = 16; o > 0; o >>= 1) part += __shfl_xor_sync(0xffffffffu, part, o);
    if (lane == 0) p.o_sigma[b] = part + __ldg(p.bs);
    #pragma unroll
    for (int s = 0; s < 8; s++) {
      p.o_out[(size_t)b * 512 + s * 64 + lane] = ar[s * S_A + lane];
      p.o_out[(size_t)b * 512 + s * 64 + lane + 32] = ar[s * S_A + lane + 32];
    }
  }

  // ---------------- cross attention + color ----------------
  float* qr = s_ao + ray * S_A;  // query row (warp-local)
  qr[lane] = p.query[(size_t)b * 64 + lane];
  qr[lane + 32] = p.query[(size_t)b * 64 + lane + 32];
  __syncwarp();

  float ca0 = 0.f, ca1 = 0.f;
  for (int h = 0; h < 4; h++) {
    __syncthreads();   // protect weight bufs from previous head's scalar readers
    stage_w(p.cWk + h * 64, 256, s_w0, tid);
    stage_w(p.cWv + h * 64, 256, s_w1, tid);
    stage_w(p.cWq + h * 64, 256, s_w3, tid);
    stage_w(p.cWo + h * 4096, 64, s_w2, tid);
    __syncthreads();
    // fused cK, cV gemms (tensor)
    {
      float ck[4][4] = {}, cv[4][4] = {};
      gemm2_acc(s_act, s_w0, s_w1, lane, mt, nh, ck, cv);
      store_c(s_k, lane, mt, nh, ck, p.cbk + h * 64, 0, nullptr);
      store_c(s_v, lane, mt, nh, cv, p.cbv + h * 64, 0, nullptr);
    }
    __syncthreads();
    // per-ray scalar: cq, scores, softmax, ctx, ca accum
    float cq0 = __ldg(p.cbq + h * 64 + lane);
    float cq1 = __ldg(p.cbq + h * 64 + lane + 32);
    #pragma unroll 8
    for (int k = 0; k < 64; k++) {
      float a = qr[k];
      cq0 = fmaf(a, s_w3[k * S_W + lane], cq0);
      cq1 = fmaf(a, s_w3[k * S_W + lane + 32], cq1);
    }
    const float* kb = s_k + ray * 8 * S_A;
    const float* vb = s_v + ray * 8 * S_A;
    float e[8];
    #pragma unroll
    for (int k = 0; k < 8; k++) {
      float pk = cq0 * kb[k * S_A + lane] + cq1 * kb[k * S_A + lane + 32];
      #pragma unroll
      for (int o = 16; o > 0; o >>= 1) pk += __shfl_xor_sync(0xffffffffu, pk, o);
      e[k] = pk * 0.125f;
    }
    float mm = e[0];
    #pragma unroll
    for (int k = 1; k < 8; k++) mm = fmaxf(mm, e[k]);
    float prb[8], sum = 0.f;
    #pragma unroll
    for (int k = 0; k < 8; k++) { prb[k] = __expf(e[k] - mm); sum += prb[k]; }
    float inv = __fdividef(1.f, sum);
    float cx0 = 0.f, cx1 = 0.f;
    #pragma unroll
    for (int k = 0; k < 8; k++) {
      float pk = prb[k] * inv;
      cx0 = fmaf(pk, vb[k * S_A + lane], cx0);
      cx1 = fmaf(pk, vb[k * S_A + lane + 32], cx1);
    }
    float* cr = s_ctx + ray * S_A;
    cr[lane] = cx0;
    cr[lane + 32] = cx1;
    __syncwarp();
    if (h == 0) { ca0 = __ldg(p.cbo + lane); ca1 = __ldg(p.cbo + lane + 32); }
    #pragma unroll 8
    for (int k = 0; k < 64; k++) {
      float a = cr[k];
      ca0 = fmaf(a, s_w2[k * S_W + lane], ca0);
      ca1 = fmaf(a, s_w2[k * S_W + lane + 32], ca1);
    }
  }

  // color = relu(ca) @ Wc + bc
  {
    float r0 = fmaxf(ca0, 0.f), r1 = fmaxf(ca1, 0.f);
    #pragma unroll
    for (int t = 0; t < 3; t++) {
      float part = r0 * __ldg(p.Wc + lane * 3 + t) + r1 * __ldg(p.Wc + (lane + 32) * 3 + t);
      #pragma unroll
      for (int o = 16; o > 0; o >>= 1) part += __shfl_xor_sync(0xffffffffu, part, o);
      if (lane == 0) p.o_color[(size_t)b * 3 + t] = part + __ldg(p.bc + t);
    }
  }
}

extern "C" void kernel_launch(void* const* d_in, const int* in_sizes, int n_in,
                              void* d_out, int out_size) {
  Params p;
  p.query = (const float*)d_in[0];
  p.latent = (const float*)d_in[1];
  p.W1 = (const float*)d_in[2];
  p.b1 = (const float*)d_in[3];
  p.Wq = (const float*)d_in[4];
  p.bq = (const float*)d_in[5];
  p.Wk = (const float*)d_in[6];
  p.bk = (const float*)d_in[7];
  p.Wv = (const float*)d_in[8];
  p.bv = (const float*)d_in[9];
  p.Wo = (const float*)d_in[10];
  p.bo = (const float*)d_in[11];
  p.fW1 = (const float*)d_in[12];
  p.fb1 = (const float*)d_in[13];
  p.fW2 = (const float*)d_in[14];
  p.fb2 = (const float*)d_in[15];
  p.g1 = (const float*)d_in[16];
  p.be1 = (const float*)d_in[17];
  p.g2 = (const float*)d_in[18];
  p.be2 = (const float*)d_in[19];
  p.cWq = (const float*)d_in[20];
  p.cbq = (const float*)d_in[21];
  p.cWk = (const float*)d_in[22];
  p.cbk = (const float*)d_in[23];
  p.cWv = (const float*)d_in[24];
  p.cbv = (const float*)d_in[25];
  p.cWo = (const float*)d_in[26];
  p.cbo = (const float*)d_in[27];
  p.Wc = (const float*)d_in[28];
  p.bc = (const float*)d_in[29];
  p.Ws = (const float*)d_in[30];
  p.bs = (const float*)d_in[31];

  float* o = (float*)d_out;
  p.o_color = o;                                    // [B,1,3]
  p.o_sigma = o + (size_t)B_TOTAL * 3;              // [B,1]
  p.o_out = o + (size_t)B_TOTAL * 4;                // [B,8,64]
  p.o_attn = o + (size_t)B_TOTAL * 4 + (size_t)B_TOTAL * 512;  // [B,4,4,8,8]

  cudaFuncSetAttribute(rt_kernel, cudaFuncAttributeMaxDynamicSharedMemorySize,
                       SMEM_BYTES);
  rt_kernel<<<NBLOCKS, NTHREADS, SMEM_BYTES>>>(p);
}